// round 7
// baseline (speedup 1.0000x reference)
#include <cuda_runtime.h>
#include <math.h>

#define BATCH 256
#define TLEN  50
#define NOBS  8192
#define NKC   50

// ---- device-global scratch (no allocations allowed) ----
__device__ unsigned char g_assign[NOBS];                 // assign[] as uint8
__device__ float         g_probs_scratch[BATCH * TLEN];  // fallback sink

// ============================================================
// k1: recover assign[] from one-hot A. Two independent float4
// loads per thread (MLP=2), 200 blocks x 256.
// ============================================================
__global__ __launch_bounds__(256)
void k1_prep(const float4* __restrict__ A4) {
    const int half = NOBS * NKC / 8;              // 51200 float4s per half
    int idx = blockIdx.x * 256 + threadIdx.x;
    float4 v0 = A4[idx];
    float4 v1 = A4[idx + half];

    int b0 = idx * 4;
    if (v0.x > 0.5f) { int i = b0 + 0; g_assign[i / NKC] = (unsigned char)(i % NKC); }
    if (v0.y > 0.5f) { int i = b0 + 1; g_assign[i / NKC] = (unsigned char)(i % NKC); }
    if (v0.z > 0.5f) { int i = b0 + 2; g_assign[i / NKC] = (unsigned char)(i % NKC); }
    if (v0.w > 0.5f) { int i = b0 + 3; g_assign[i / NKC] = (unsigned char)(i % NKC); }

    int b1 = (idx + half) * 4;
    if (v1.x > 0.5f) { int i = b1 + 0; g_assign[i / NKC] = (unsigned char)(i % NKC); }
    if (v1.y > 0.5f) { int i = b1 + 1; g_assign[i / NKC] = (unsigned char)(i % NKC); }
    if (v1.z > 0.5f) { int i = b1 + 2; g_assign[i / NKC] = (unsigned char)(i % NKC); }
    if (v1.w > 0.5f) { int i = b1 + 3; g_assign[i / NKC] = (unsigned char)(i % NKC); }
}

__device__ __forceinline__ float sigm(float x) {
    return 1.0f / (1.0f + __expf(-x));
}

// ============================================================
// k2: fused BKT, one block (256 thr) per batch row.
//  - prologue: ONE sync; per-step tables built independently per
//    thread; expansion's assign bytes preloaded into registers
//    (LDG overlaps everything).
//  - recurrence: warp 0, homogeneous (u,v) state in registers,
//    carried chain = shfl + 2 FMA + SEL (~34 cyc). Divisions only
//    off-chain.
//  - tail: LDS gather + float4 stores only.
// ============================================================
__global__ __launch_bounds__(256, 4)
void k2_fused(const int*   __restrict__ prev_kc,
              const int*   __restrict__ curr_kc,
              const float* __restrict__ prev_corr,
              const float* __restrict__ kc_logits,
              float*       __restrict__ probs_out,
              float*       __restrict__ state_out,
              int do_state) {
    __shared__ float4        s_M[TLEN];     // Moebius (A,B,C,D) per step
    __shared__ float2        s_ozw[TLEN];   // (p3-p2, p2) at ack KC
    __shared__ float         s_p4[NKC];     // initial state per KC
    __shared__ float         s_state[NKC];  // final compact state
    __shared__ unsigned char s_ap[TLEN];
    __shared__ unsigned char s_ack[TLEN];

    const int b   = blockIdx.x;
    const int tid = threadIdx.x;

    // --- preload expansion assign bytes into registers (overlaps all) ---
    uchar4 areg[8];
    {
        const uchar4* ga4 = (const uchar4*)g_assign;
        #pragma unroll
        for (int j = 0; j < 8; j++) areg[j] = ga4[tid + 256 * j];
    }

    // --- per-step tables, fully independent per thread (t = tid) ---
    if (tid < TLEN) {
        int   pkv = prev_kc[b * TLEN + tid];
        int   ckv = curr_kc[b * TLEN + tid];
        float cr  = prev_corr[b * TLEN + tid];

        int ap = g_assign[pkv];
        int ac = g_assign[ckv];
        s_ap[tid]  = (unsigned char)ap;
        s_ack[tid] = (unsigned char)ac;

        // probs of the KC of pk (only the 4 needed)
        float pl = sigm(kc_logits[ap * 5 + 0]);
        float pf = sigm(kc_logits[ap * 5 + 1]);
        float p2 = sigm(kc_logits[ap * 5 + 2]);
        float p3 = sigm(kc_logits[ap * 5 + 3]);

        float o0, o1;
        if (cr > 0.5f) { o0 = p2;        o1 = p3;        }
        else           { o0 = 1.0f - p2; o1 = 1.0f - p3; }
        float d10 = o1 - o0;
        float c1  = 1.0f - pf - pl;
        // pred = (A*s + B) / (C*s + D)
        s_M[tid] = make_float4(fmaf(pl, d10, c1 * o1), pl * o0, d10, o0);

        // output coefficients at ack KC
        float q2 = sigm(kc_logits[ac * 5 + 2]);
        float q3 = sigm(kc_logits[ac * 5 + 3]);
        s_ozw[tid] = make_float2(q3 - q2, q2);

        // initial state for KC tid
        s_p4[tid] = sigm(kc_logits[tid * 5 + 4]);
    }
    __syncthreads();

    // --- recurrence: warp 0, homogeneous register state ---
    if (tid < 32) {
        const int lane = tid;
        float u0 = s_p4[lane], v0 = 1.0f;                              // KC lane
        float u1 = (lane < NKC - 32) ? s_p4[lane + 32] : 0.0f;         // KC lane+32
        float v1 = 1.0f;

        float* out = probs_out + b * TLEN;

        // t = 0: prediction from initial state
        if (lane == 0) {
            float2 zw = s_ozw[0];
            out[0] = fmaf(zw.x, s_p4[s_ack[0]], zw.y);
        }

        #pragma unroll
        for (int t = 1; t < TLEN; t++) {
            int    ap = (int)s_ap[t];
            float4 M  = s_M[t];

            int src = ap & 31;
            float su0 = __shfl_sync(0xffffffffu, u0, src);
            float sv0 = __shfl_sync(0xffffffffu, v0, src);
            float su1 = __shfl_sync(0xffffffffu, u1, src);
            float sv1 = __shfl_sync(0xffffffffu, v1, src);
            float us  = (ap < 32) ? su0 : su1;
            float vs  = (ap < 32) ? sv0 : sv1;

            float nu = fmaf(M.x, us, M.y * vs);
            float nv = fmaf(M.z, us, M.w * vs);

            if (lane == ap)      { u0 = nu; v0 = nv; }
            if (lane == ap - 32) { u1 = nu; v1 = nv; }

            // output (off the carried chain)
            int ac = (int)s_ack[t];
            int sc = ac & 31;
            float ou0 = __shfl_sync(0xffffffffu, u0, sc);
            float ov0 = __shfl_sync(0xffffffffu, v0, sc);
            float ou1 = __shfl_sync(0xffffffffu, u1, sc);
            float ov1 = __shfl_sync(0xffffffffu, v1, sc);
            if (lane == 0) {
                float cu = (ac < 32) ? ou0 : ou1;
                float cv = (ac < 32) ? ov0 : ov1;
                float cs = __fdividef(cu, cv);
                float2 zw = s_ozw[t];
                out[t] = fmaf(zw.x, cs, zw.y);
            }
        }

        // publish final compact state
        s_state[lane] = __fdividef(u0, v0);
        if (lane < NKC - 32) s_state[lane + 32] = __fdividef(u1, v1);
    }
    __syncthreads();

    // --- expansion tail: LDS gathers + float4 stores only ---
    if (do_state) {
        float4* o = (float4*)(state_out + (size_t)b * NOBS);
        #pragma unroll
        for (int j = 0; j < 8; j++) {
            uchar4 a = areg[j];
            o[tid + 256 * j] =
                make_float4(s_state[a.x], s_state[a.y], s_state[a.z], s_state[a.w]);
        }
    }
}

// ============================================================
extern "C" void kernel_launch(void* const* d_in, const int* in_sizes, int n_in,
                              void* d_out, int out_size) {
    const int*    prev_kc   = (const int*)   d_in[0];
    const int*    curr_kc   = (const int*)   d_in[1];
    const float*  prev_corr = (const float*) d_in[2];
    const float*  kc_logits = (const float*) d_in[3];
    const float4* A4        = (const float4*)d_in[4];
    float*        out       = (float*)d_out;

    k1_prep<<<(NOBS * NKC / 8) / 256, 256>>>(A4);

    // Output layout: [probs (256*50) | state (256*8192)] concatenated.
    float* probs_out = out;
    float* state_out = out + BATCH * TLEN;
    int    do_state  = 1;

    if (out_size == BATCH * TLEN) {
        do_state  = 0;
        state_out = out;                 // unused
    } else if (out_size == BATCH * NOBS) {
        void* scratch = nullptr;
        cudaGetSymbolAddress(&scratch, g_probs_scratch);
        probs_out = (float*)scratch;
        state_out = out;
    }

    k2_fused<<<BATCH, 256>>>(prev_kc, curr_kc, prev_corr, kc_logits,
                             probs_out, state_out, do_state);
}

// round 8
// speedup vs baseline: 1.0022x; 1.0022x over previous
#include <cuda_runtime.h>
#include <math.h>

#define BATCH 256
#define TLEN  50
#define NOBS  8192
#define NKC   50
#define F4_PER_BLK (NOBS * NKC / 4 / BATCH)   // 400 float4s of A per block

// ---- device-global scratch (no allocations allowed) ----
__device__ unsigned char      g_assign[NOBS];
__device__ float              g_probs_scratch[BATCH * TLEN];
__device__ unsigned long long g_bar;          // monotone epoch barrier counter

__device__ __forceinline__ float sigm(float x) {
    return 1.0f / (1.0f + __expf(-x));
}

// ============================================================
// Single fused kernel, 256 blocks x 256 threads, all co-resident.
// Phase 1: each block scans its 1/256 slice of A -> g_assign bytes.
//          (overlapped: row inputs + all 250 sigmoids load in parallel)
// Grid barrier (epoch counter, graph-replay safe).
// Phase 2: per-step Moebius tables -> warp-0 register recurrence
//          (2 shfl/step) -> expansion with register-preloaded assign.
// ============================================================
__global__ __launch_bounds__(256, 2)
void bkt_fused(const float4* __restrict__ A4,
               const int*    __restrict__ prev_kc,
               const int*    __restrict__ curr_kc,
               const float*  __restrict__ prev_corr,
               const float*  __restrict__ kc_logits,
               float*        __restrict__ probs_out,
               float*        __restrict__ state_out,
               int do_state) {
    __shared__ float4        s_pr[NKC];     // sigmoid(pl,pf,p2,p3)
    __shared__ float         s_p4[NKC];     // initial state per KC
    __shared__ float4        s_M[TLEN];     // Moebius (A,B,C,D) per step
    __shared__ float2        s_ozw[TLEN];   // (q3-q2, q2) at ack KC
    __shared__ float         s_state[NKC];  // final compact state
    __shared__ unsigned char s_ap[TLEN];
    __shared__ unsigned char s_ack[TLEN];

    const int b    = blockIdx.x;
    const int tid  = threadIdx.x;
    const int lane = tid & 31;

    // ---- issue ALL independent loads up front ----
    int   pkv = 0, ckv = 0;
    float cr  = 0.0f;
    if (tid < TLEN) {
        pkv = prev_kc[b * TLEN + tid];
        ckv = curr_kc[b * TLEN + tid];
        cr  = prev_corr[b * TLEN + tid];
    }

    // phase 1: this block's slice of A (400 float4s)
    {
        const float4* src = A4 + b * F4_PER_BLK;
        #pragma unroll
        for (int i = tid; i < F4_PER_BLK; i += 256) {
            float4 v = src[i];
            int base = (b * F4_PER_BLK + i) * 4;
            if (v.x > 0.5f) { int j = base + 0; g_assign[j / NKC] = (unsigned char)(j % NKC); }
            if (v.y > 0.5f) { int j = base + 1; g_assign[j / NKC] = (unsigned char)(j % NKC); }
            if (v.z > 0.5f) { int j = base + 2; g_assign[j / NKC] = (unsigned char)(j % NKC); }
            if (v.w > 0.5f) { int j = base + 3; g_assign[j / NKC] = (unsigned char)(j % NKC); }
        }
    }

    // sigmoids for all KCs (independent of assign)
    if (tid < NKC) {
        float4 p;
        p.x = sigm(kc_logits[tid * 5 + 0]);
        p.y = sigm(kc_logits[tid * 5 + 1]);
        p.z = sigm(kc_logits[tid * 5 + 2]);
        p.w = sigm(kc_logits[tid * 5 + 3]);
        s_pr[tid] = p;
        s_p4[tid] = sigm(kc_logits[tid * 5 + 4]);
    }

    // ---- grid barrier (release: fence-all, arrive; acquire: spin+fence) ----
    __threadfence();     // release this thread's g_assign writes
    __syncthreads();     // all block writes fenced before arrive
    if (tid == 0) {
        unsigned long long old =
            atomicAdd(&g_bar, 1ULL);
        unsigned long long target = (old / (unsigned long long)BATCH + 1ULL)
                                    * (unsigned long long)BATCH;
        volatile unsigned long long* pc = &g_bar;
        while (*pc < target) { __nanosleep(32); }
        __threadfence();  // acquire
    }
    __syncthreads();

    // ---- preload expansion assign bytes (overlaps table build + recurrence) ----
    uchar4 areg[8];
    {
        const uchar4* ga4 = (const uchar4*)g_assign;
        #pragma unroll
        for (int j = 0; j < 8; j++) areg[j] = ga4[tid + 256 * j];
    }

    // ---- per-step tables (threads 0..49) ----
    if (tid < TLEN) {
        int ap = g_assign[pkv];
        int ac = g_assign[ckv];
        s_ap[tid]  = (unsigned char)ap;
        s_ack[tid] = (unsigned char)ac;

        float4 pp = s_pr[ap];
        float o0, o1;
        if (cr > 0.5f) { o0 = pp.z;        o1 = pp.w;        }
        else           { o0 = 1.0f - pp.z; o1 = 1.0f - pp.w; }
        float d10 = o1 - o0;
        float c1  = 1.0f - pp.y - pp.x;
        // pred = (A*s + B) / (C*s + D)
        s_M[tid] = make_float4(fmaf(pp.x, d10, c1 * o1), pp.x * o0, d10, o0);

        float4 q = s_pr[ac];
        s_ozw[tid] = make_float2(q.w - q.z, q.z);
    }
    __syncthreads();

    // ---- recurrence: warp 0, homogeneous register state, 2 shfl/step ----
    if (tid < 32) {
        float u0 = s_p4[lane], v0 = 1.0f;                       // KC lane
        float u1 = (lane < NKC - 32) ? s_p4[lane + 32] : 0.0f;  // KC lane+32
        float v1 = 1.0f;

        float* out = probs_out + b * TLEN;

        // t = 0: prediction from initial state (owning lane stores)
        {
            int ac = (int)s_ack[0];
            if (lane == (ac & 31)) {
                float s0 = (ac < 32) ? u0 : u1;   // v == 1 initially
                float2 zw = s_ozw[0];
                out[0] = fmaf(zw.x, s0, zw.y);
            }
        }

        #pragma unroll
        for (int t = 1; t < TLEN; t++) {
            int    ap = (int)s_ap[t];
            float4 M  = s_M[t];

            // donor-select: every lane offers the pair the step needs
            float du = (ap < 32) ? u0 : u1;
            float dv = (ap < 32) ? v0 : v1;
            float us = __shfl_sync(0xffffffffu, du, ap & 31);
            float vs = __shfl_sync(0xffffffffu, dv, ap & 31);

            float nu = fmaf(M.x, us, M.y * vs);
            float nv = fmaf(M.z, us, M.w * vs);

            if (lane == ap)      { u0 = nu; v0 = nv; }
            if (lane == ap - 32) { u1 = nu; v1 = nv; }

            // output: owning lane stores (division off the carried chain)
            int ac = (int)s_ack[t];
            if (lane == (ac & 31)) {
                float cu = (ac < 32) ? u0 : u1;
                float cv = (ac < 32) ? v0 : v1;
                float2 zw = s_ozw[t];
                out[t] = fmaf(zw.x, __fdividef(cu, cv), zw.y);
            }
        }

        s_state[lane] = __fdividef(u0, v0);
        if (lane < NKC - 32) s_state[lane + 32] = __fdividef(u1, v1);
    }
    __syncthreads();

    // ---- expansion: LDS gathers + float4 stores ----
    if (do_state) {
        float4* o = (float4*)(state_out + (size_t)b * NOBS);
        #pragma unroll
        for (int j = 0; j < 8; j++) {
            uchar4 a = areg[j];
            o[tid + 256 * j] =
                make_float4(s_state[a.x], s_state[a.y], s_state[a.z], s_state[a.w]);
        }
    }
}

// ============================================================
extern "C" void kernel_launch(void* const* d_in, const int* in_sizes, int n_in,
                              void* d_out, int out_size) {
    const int*    prev_kc   = (const int*)   d_in[0];
    const int*    curr_kc   = (const int*)   d_in[1];
    const float*  prev_corr = (const float*) d_in[2];
    const float*  kc_logits = (const float*) d_in[3];
    const float4* A4        = (const float4*)d_in[4];
    float*        out       = (float*)d_out;

    // Output layout: [probs (256*50) | state (256*8192)] concatenated.
    float* probs_out = out;
    float* state_out = out + BATCH * TLEN;
    int    do_state  = 1;

    if (out_size == BATCH * TLEN) {
        do_state  = 0;
        state_out = out;                 // unused
    } else if (out_size == BATCH * NOBS) {
        void* scratch = nullptr;
        cudaGetSymbolAddress(&scratch, g_probs_scratch);
        probs_out = (float*)scratch;
        state_out = out;
    }

    bkt_fused<<<BATCH, 256>>>(A4, prev_kc, curr_kc, prev_corr, kc_logits,
                              probs_out, state_out, do_state);
}

// round 9
// speedup vs baseline: 1.3528x; 1.3499x over previous
#include <cuda_runtime.h>
#include <math.h>

#define BATCH 256
#define TLEN  50
#define NOBS  8192
#define NKC   50

// ---- device-global scratch (no allocations allowed) ----
__device__ unsigned char g_assign[NOBS];                 // assign[] as uint8
__device__ float         g_probs_scratch[BATCH * TLEN];  // fallback sink

__device__ __forceinline__ float sigm(float x) {
    return 1.0f / (1.0f + __expf(-x));
}

// ============================================================
// k1: recover assign[] from one-hot A. Two independent float4
// loads per thread (MLP=2), 200 blocks x 256.
// ============================================================
__global__ __launch_bounds__(256)
void k1_prep(const float4* __restrict__ A4) {
    const int half = NOBS * NKC / 8;              // 51200 float4s per half
    int idx = blockIdx.x * 256 + threadIdx.x;
    float4 v0 = A4[idx];
    float4 v1 = A4[idx + half];

    int b0 = idx * 4;
    if (v0.x > 0.5f) { int i = b0 + 0; g_assign[i / NKC] = (unsigned char)(i % NKC); }
    if (v0.y > 0.5f) { int i = b0 + 1; g_assign[i / NKC] = (unsigned char)(i % NKC); }
    if (v0.z > 0.5f) { int i = b0 + 2; g_assign[i / NKC] = (unsigned char)(i % NKC); }
    if (v0.w > 0.5f) { int i = b0 + 3; g_assign[i / NKC] = (unsigned char)(i % NKC); }

    int b1 = (idx + half) * 4;
    if (v1.x > 0.5f) { int i = b1 + 0; g_assign[i / NKC] = (unsigned char)(i % NKC); }
    if (v1.y > 0.5f) { int i = b1 + 1; g_assign[i / NKC] = (unsigned char)(i % NKC); }
    if (v1.z > 0.5f) { int i = b1 + 2; g_assign[i / NKC] = (unsigned char)(i % NKC); }
    if (v1.w > 0.5f) { int i = b1 + 3; g_assign[i / NKC] = (unsigned char)(i % NKC); }
}

// ============================================================
// k2: fused BKT, one block (128 thr) per batch row.
//  - prologue: g_assign -> shared copy (overlaps scalar loads),
//    sigmoids into s_pr; one LDS-only gather phase builds the
//    per-step Moebius tables.
//  - core: NO serial chain. Pass A (threads 0..49): out[t] from
//    the composition of {M_i : i<=t, ap_i==ck_t}. Pass B (threads
//    64..113): final state[k] from {M_i : ap_i==k}. Branch-free
//    select-to-identity compose, unroll 7 -> issue-bound.
//  - tail: expansion via LDS gathers + float4 stores.
// ============================================================
__global__ __launch_bounds__(128, 4)
void k2_fused(const int*   __restrict__ prev_kc,
              const int*   __restrict__ curr_kc,
              const float* __restrict__ prev_corr,
              const float* __restrict__ kc_logits,
              float*       __restrict__ probs_out,
              float*       __restrict__ state_out,
              int do_state) {
    __shared__ unsigned char s_assign[NOBS];   // 8 KB
    __shared__ float4        s_pr[NKC];        // sigmoid(pl,pf,p2,p3)
    __shared__ float         s_p4[NKC];        // initial state per KC
    __shared__ float4        s_M[TLEN];        // Moebius (A,B,C,D) per step
    __shared__ float2        s_ozw[TLEN];      // (q3-q2, q2) at ack KC
    __shared__ float         s_state[NKC];     // final compact state
    __shared__ unsigned char s_ap[TLEN];
    __shared__ unsigned char s_ack[TLEN];

    const int b   = blockIdx.x;
    const int tid = threadIdx.x;

    // --- copy g_assign -> shared (coalesced int4, overlaps loads below) ---
    {
        const int4* src = (const int4*)g_assign;
        int4*       dst = (int4*)s_assign;
        #pragma unroll
        for (int i = 0; i < 4; i++) dst[tid + 128 * i] = src[tid + 128 * i];
    }

    // --- scalar row inputs + per-KC sigmoids (threads 0..49) ---
    int   pkv = 0, ckv = 0;
    float cr  = 0.0f;
    if (tid < TLEN) {
        pkv = prev_kc[b * TLEN + tid];
        ckv = curr_kc[b * TLEN + tid];
        cr  = prev_corr[b * TLEN + tid];

        float4 p;
        p.x = sigm(kc_logits[tid * 5 + 0]);
        p.y = sigm(kc_logits[tid * 5 + 1]);
        p.z = sigm(kc_logits[tid * 5 + 2]);
        p.w = sigm(kc_logits[tid * 5 + 3]);
        s_pr[tid] = p;
        s_p4[tid] = sigm(kc_logits[tid * 5 + 4]);
    }
    __syncthreads();

    // --- per-step tables: LDS-only gathers ---
    if (tid < TLEN) {
        int ap = s_assign[pkv];
        int ac = s_assign[ckv];
        s_ap[tid]  = (unsigned char)ap;
        s_ack[tid] = (unsigned char)ac;

        float4 pp = s_pr[ap];
        float o0, o1;
        if (cr > 0.5f) { o0 = pp.z;        o1 = pp.w;        }
        else           { o0 = 1.0f - pp.z; o1 = 1.0f - pp.w; }
        float d10 = o1 - o0;
        float c1  = 1.0f - pp.y - pp.x;
        // pred = (A*s + B) / (C*s + D)
        s_M[tid] = make_float4(fmaf(pp.x, d10, c1 * o1), pp.x * o0, d10, o0);

        float4 q = s_pr[ac];
        s_ozw[tid] = make_float2(q.w - q.z, q.z);
    }
    __syncthreads();

    // --- parallel Moebius composition (no serial chain) ---
    if (tid < TLEN) {
        // pass A: out[t], t = tid. t=0 composes nothing -> identity. 
        const int t = tid;
        const int k = (int)s_ack[t];
        float a = 1.0f, bm = 0.0f, c = 0.0f, d = 1.0f;
        #pragma unroll 7
        for (int i = 1; i < TLEN; i++) {
            float4 M = s_M[i];                            // broadcast LDS
            bool take = (i <= t) && ((int)s_ap[i] == k);
            float Mx = take ? M.x : 1.0f;
            float My = take ? M.y : 0.0f;
            float Mz = take ? M.z : 0.0f;
            float Mw = take ? M.w : 1.0f;
            float na = fmaf(Mx, a,  My * c);
            float nb = fmaf(Mx, bm, My * d);
            float nc = fmaf(Mz, a,  Mw * c);
            float nd = fmaf(Mz, bm, Mw * d);
            a = na; bm = nb; c = nc; d = nd;
        }
        float s0 = s_p4[k];
        float sf = __fdividef(fmaf(a, s0, bm), fmaf(c, s0, d));
        float2 zw = s_ozw[t];
        probs_out[b * TLEN + t] = fmaf(zw.x, sf, zw.y);
    } else if (tid >= 64 && tid < 64 + NKC) {
        // pass B: final state[k], k = tid-64 (separate warps, concurrent)
        const int k = tid - 64;
        float a = 1.0f, bm = 0.0f, c = 0.0f, d = 1.0f;
        #pragma unroll 7
        for (int i = 1; i < TLEN; i++) {
            float4 M = s_M[i];
            bool take = ((int)s_ap[i] == k);
            float Mx = take ? M.x : 1.0f;
            float My = take ? M.y : 0.0f;
            float Mz = take ? M.z : 0.0f;
            float Mw = take ? M.w : 1.0f;
            float na = fmaf(Mx, a,  My * c);
            float nb = fmaf(Mx, bm, My * d);
            float nc = fmaf(Mz, a,  Mw * c);
            float nd = fmaf(Mz, bm, Mw * d);
            a = na; bm = nb; c = nc; d = nd;
        }
        float s0 = s_p4[k];
        s_state[k] = __fdividef(fmaf(a, s0, bm), fmaf(c, s0, d));
    }
    __syncthreads();

    // --- expansion: LDS gathers + float4 stores (16 per thread) ---
    if (do_state) {
        float4*       o  = (float4*)(state_out + (size_t)b * NOBS);
        const uchar4* a4 = (const uchar4*)s_assign;
        #pragma unroll
        for (int j = 0; j < 16; j++) {
            uchar4 a = a4[tid + 128 * j];
            o[tid + 128 * j] =
                make_float4(s_state[a.x], s_state[a.y], s_state[a.z], s_state[a.w]);
        }
    }
}

// ============================================================
extern "C" void kernel_launch(void* const* d_in, const int* in_sizes, int n_in,
                              void* d_out, int out_size) {
    const int*    prev_kc   = (const int*)   d_in[0];
    const int*    curr_kc   = (const int*)   d_in[1];
    const float*  prev_corr = (const float*) d_in[2];
    const float*  kc_logits = (const float*) d_in[3];
    const float4* A4        = (const float4*)d_in[4];
    float*        out       = (float*)d_out;

    k1_prep<<<(NOBS * NKC / 8) / 256, 256>>>(A4);

    // Output layout: [probs (256*50) | state (256*8192)] concatenated.
    float* probs_out = out;
    float* state_out = out + BATCH * TLEN;
    int    do_state  = 1;

    if (out_size == BATCH * TLEN) {
        do_state  = 0;
        state_out = out;                 // unused
    } else if (out_size == BATCH * NOBS) {
        void* scratch = nullptr;
        cudaGetSymbolAddress(&scratch, g_probs_scratch);
        probs_out = (float*)scratch;
        state_out = out;
    }

    k2_fused<<<BATCH, 128>>>(prev_kc, curr_kc, prev_corr, kc_logits,
                             probs_out, state_out, do_state);
}